// round 7
// baseline (speedup 1.0000x reference)
#include <cuda_runtime.h>
#include <cuda_fp16.h>
#include <math.h>

#define N_NODES 50000
#define N_EDGES 640000
#define N_GRAPHS 64
#define D 128
#define SCAN_B ((N_NODES + 255) / 256)   // 196

// ---------------- device scratch (no allocation allowed) ----------------
__device__ __half  g_xph[N_NODES * D];   // xp in fp16 (gather operand)
__device__ float   g_h [N_NODES * D];    // layer output (bias+relu applied), fp32
__device__ float2  g_si[N_NODES];        // per-node dst-attention dots (2 heads)
__device__ float2  g_sj[N_NODES];        // per-node src-attention dots
__device__ float   g_ae[36];             // 3 layers x 6 feats x 2 heads
__device__ float2  g_seS[3 * N_EDGES];   // per-edge edge-att scores, dst-sorted, per layer
__device__ int     g_srcs[N_EDGES];      // src ids sorted by dst
__device__ int     g_deg[N_NODES];
__device__ int     g_off[N_NODES + 1];
__device__ int     g_cur[N_NODES];
__device__ int     g_bsum[SCAN_B];
__device__ float   g_pool[N_GRAPHS * D];
__device__ float   g_cnt[N_GRAPHS];
__device__ int     g_flags[2];           // [0]: edge_index is int64, [1]: batch is int64

// -------- init: dtype detection + per-layer edge-att projection ----------
__global__ void init_kernel(const int* __restrict__ ei32, const int* __restrict__ b32,
                            const float* __restrict__ we0, const float* __restrict__ at0,
                            const float* __restrict__ we1, const float* __restrict__ at1,
                            const float* __restrict__ we2, const float* __restrict__ at2) {
    __shared__ int s_e, s_b;
    int t = threadIdx.x;
    if (t == 0) { s_e = 0; s_b = 0; }
    __syncthreads();
    int ei_idx = 2 * (t * 257) + 1;
    if (ei32[ei_idx] != 0) atomicAdd(&s_e, 1);
    int b_idx = (N_NODES - 1) - 2 * t;     // batch sorted: sample near tail
    if (b32[b_idx] != 0) atomicAdd(&s_b, 1);
    __syncthreads();
    if (t == 0) { g_flags[0] = (s_e == 0); g_flags[1] = (s_b == 0); }
    if (t < 36) {
        int l = t / 12, r = t % 12, f = r / 2, h = r % 2;
        const float* we = (l == 0) ? we0 : (l == 1) ? we1 : we2;
        const float* at = (l == 0) ? at0 : (l == 1) ? at1 : at2;
        float s = 0.f;
        #pragma unroll
        for (int c = 0; c < 64; c++)
            s += we[f * 128 + h * 64 + c] * at[h * 192 + 128 + c];
        g_ae[t] = s;
    }
}

__device__ __forceinline__ void load_edge(const void* ei, int e, int& src, int& dst) {
    if (g_flags[0]) {
        const long long* p = (const long long*)ei;
        src = (int)p[e]; dst = (int)p[N_EDGES + e];
    } else {
        const int* p = (const int*)ei;
        src = p[e]; dst = p[N_EDGES + e];
    }
}

// ---------------------------- CSR build ----------------------------------
__global__ void deg_kernel(const void* __restrict__ ei) {
    int e = blockIdx.x * blockDim.x + threadIdx.x;
    if (e >= N_EDGES) return;
    int src, dst; load_edge(ei, e, src, dst);
    atomicAdd(&g_deg[dst], 1);
}

__global__ void scan1_kernel() {              // SCAN_B blocks x 256
    __shared__ int sh[256];
    int t = threadIdx.x;
    int i = blockIdx.x * 256 + t;
    int v = (i < N_NODES) ? g_deg[i] : 0;
    sh[t] = v; __syncthreads();
    #pragma unroll
    for (int off = 1; off < 256; off <<= 1) {
        int u = (t >= off) ? sh[t - off] : 0;
        __syncthreads();
        sh[t] += u;
        __syncthreads();
    }
    if (i < N_NODES) g_off[i] = sh[t] - v;    // block-local exclusive
    if (t == 255) g_bsum[blockIdx.x] = sh[255];
}

__global__ void scan2_kernel() {              // 1 block x 256
    __shared__ int sh[256];
    int t = threadIdx.x;
    int v = (t < SCAN_B) ? g_bsum[t] : 0;
    sh[t] = v; __syncthreads();
    #pragma unroll
    for (int off = 1; off < 256; off <<= 1) {
        int u = (t >= off) ? sh[t - off] : 0;
        __syncthreads();
        sh[t] += u;
        __syncthreads();
    }
    if (t < SCAN_B) g_bsum[t] = sh[t] - v;    // exclusive block prefix
}

__global__ void scan3_kernel() {              // SCAN_B blocks x 256
    int i = blockIdx.x * 256 + threadIdx.x;
    if (i < N_NODES) {
        int o = g_off[i] + g_bsum[blockIdx.x];
        g_off[i] = o; g_cur[i] = o;
    }
    if (i == 0) g_off[N_NODES] = N_EDGES;
}

// scatter src + per-edge se (all 3 layers) into dst-sorted order
__global__ void scatter_kernel(const void* __restrict__ ei,
                               const float* __restrict__ ea) {
    int e = blockIdx.x * blockDim.x + threadIdx.x;
    if (e >= N_EDGES) return;
    int src, dst; load_edge(ei, e, src, dst);
    int pos = atomicAdd(&g_cur[dst], 1);
    g_srcs[pos] = src;
    float f[6];
    #pragma unroll
    for (int k = 0; k < 6; k++) f[k] = __ldg(ea + e * 6 + k);
    #pragma unroll
    for (int l = 0; l < 3; l++) {
        const float* ap = g_ae + l * 12;
        float s0 = 0.f, s1 = 0.f;
        #pragma unroll
        for (int k = 0; k < 6; k++) { s0 += f[k] * ap[k * 2]; s1 += f[k] * ap[k * 2 + 1]; }
        g_seS[l * N_EDGES + pos] = make_float2(s0, s1);
    }
}

// ---------------- layer-0 lin: x(N,7) @ w(7,128) -> g_xph ----------------
__global__ void lin0_kernel(const float* __restrict__ x, const float* __restrict__ w) {
    int idx = blockIdx.x * blockDim.x + threadIdx.x;
    if (idx >= N_NODES * D) return;
    int n = idx >> 7, c = idx & 127;
    const float* xr = x + n * 7;
    float s = 0.f;
    #pragma unroll
    for (int f = 0; f < 7; f++) s += xr[f] * w[f * 128 + c];
    g_xph[idx] = __float2half_rn(s);
}

// ------------- per-node attention dots for layer 0 (reads fp16 xp) -------
__global__ void s_kernel(const float* __restrict__ att) {
    int node = (blockIdx.x * blockDim.x + threadIdx.x) >> 5;
    int lane = threadIdx.x & 31;
    if (node >= N_NODES) return;
    uint2 raw = ((const uint2*)(g_xph + (size_t)node * D))[lane];
    __half2 p0 = *reinterpret_cast<__half2*>(&raw.x);
    __half2 p1 = *reinterpret_cast<__half2*>(&raw.y);
    float2 f0 = __half22float2(p0), f1 = __half22float2(p1);
    float v[4] = { f0.x, f0.y, f1.x, f1.y };
    float si_p = 0.f, sj_p = 0.f;
    int c0 = lane * 4;
    int h  = c0 >> 6;
    const float* ai = att + h * 192;
    const float* aj = att + h * 192 + 64;
    #pragma unroll
    for (int k = 0; k < 4; k++) {
        int cc = (c0 & 63) + k;
        si_p += v[k] * ai[cc];
        sj_p += v[k] * aj[cc];
    }
    #pragma unroll
    for (int o = 8; o; o >>= 1) {
        si_p += __shfl_down_sync(0xffffffffu, si_p, o, 16);
        sj_p += __shfl_down_sync(0xffffffffu, sj_p, o, 16);
    }
    float si1 = __shfl_sync(0xffffffffu, si_p, 16);
    float sj1 = __shfl_sync(0xffffffffu, sj_p, 16);
    if (lane == 0) {
        g_si[node] = make_float2(si_p, si1);
        g_sj[node] = make_float2(sj_p, sj1);
    }
}

// ------------- lin: h(N,128) @ w(128,128) -> g_xph, + fused s-dots -------
__global__ void lin128_kernel(const float* __restrict__ hin, const float* __restrict__ w,
                              const float* __restrict__ att) {
    __shared__ float Xs[64][33];
    __shared__ float Ws[32][128];
    int t = threadIdx.x;
    int tcol = t & 15, trow = t >> 4;
    int row0 = blockIdx.x * 64;
    float acc[4][8];
    #pragma unroll
    for (int i = 0; i < 4; i++)
        #pragma unroll
        for (int j = 0; j < 8; j++) acc[i][j] = 0.f;

    for (int kc = 0; kc < 4; kc++) {
        int k0 = kc * 32;
        for (int i = t; i < 64 * 32; i += 256) {
            int r = i >> 5, k = i & 31, row = row0 + r;
            Xs[r][k] = (row < N_NODES) ? hin[row * 128 + k0 + k] : 0.f;
        }
        for (int i = t; i < 32 * 128; i += 256) {
            int kk = i >> 7, c = i & 127;
            Ws[kk][c] = w[(k0 + kk) * 128 + c];
        }
        __syncthreads();
        #pragma unroll
        for (int kk = 0; kk < 32; kk++) {
            float xv[4];
            #pragma unroll
            for (int i = 0; i < 4; i++) xv[i] = Xs[trow * 4 + i][kk];
            #pragma unroll
            for (int j = 0; j < 8; j++) {
                float wv = Ws[kk][tcol + 16 * j];
                #pragma unroll
                for (int i = 0; i < 4; i++) acc[i][j] += xv[i] * wv;
            }
        }
        __syncthreads();
    }
    // store xp as fp16
    #pragma unroll
    for (int i = 0; i < 4; i++) {
        int row = row0 + trow * 4 + i;
        if (row < N_NODES) {
            #pragma unroll
            for (int j = 0; j < 8; j++)
                g_xph[(size_t)row * 128 + tcol + 16 * j] = __float2half_rn(acc[i][j]);
        }
    }
    // fused s-dots from fp32 accumulators
    float psi0[4] = {0,0,0,0}, psi1[4] = {0,0,0,0};
    float psj0[4] = {0,0,0,0}, psj1[4] = {0,0,0,0};
    #pragma unroll
    for (int j = 0; j < 8; j++) {
        int c = tcol + 16 * j;
        int h = c >> 6, cc = c & 63;
        float ai = att[h * 192 + cc];
        float aj = att[h * 192 + 64 + cc];
        #pragma unroll
        for (int i = 0; i < 4; i++) {
            float v = acc[i][j];
            if (h == 0) { psi0[i] += v * ai; psj0[i] += v * aj; }
            else        { psi1[i] += v * ai; psj1[i] += v * aj; }
        }
    }
    #pragma unroll
    for (int i = 0; i < 4; i++) {
        #pragma unroll
        for (int o = 8; o; o >>= 1) {
            psi0[i] += __shfl_down_sync(0xffffffffu, psi0[i], o, 16);
            psi1[i] += __shfl_down_sync(0xffffffffu, psi1[i], o, 16);
            psj0[i] += __shfl_down_sync(0xffffffffu, psj0[i], o, 16);
            psj1[i] += __shfl_down_sync(0xffffffffu, psj1[i], o, 16);
        }
    }
    if (tcol == 0) {
        #pragma unroll
        for (int i = 0; i < 4; i++) {
            int row = row0 + trow * 4 + i;
            if (row < N_NODES) {
                g_si[row] = make_float2(psi0[i], psi1[i]);
                g_sj[row] = make_float2(psj0[i], psj1[i]);
            }
        }
    }
}

// ------- aggregate: warp/dst, 4-edge unrolled, sigmoid softmax -----------
__device__ __forceinline__ float lrelu(float v) { return v > 0.f ? v : 0.2f * v; }

__global__ void __launch_bounds__(256) agg_kernel(const float* __restrict__ b, int layer) {
    int node = (blockIdx.x * blockDim.x + threadIdx.x) >> 5;
    int lane = threadIdx.x & 31;
    if (node >= N_NODES) return;
    int beg = g_off[node], end = g_off[node + 1];
    float2 si = g_si[node];
    const float2* seL = g_seS + (size_t)layer * N_EDGES;
    float4 acc = make_float4(0.f, 0.f, 0.f, 0.f);
    float sgn = (lane < 16) ? 1.f : -1.f;     // head0 = cols 0..63 (lanes 0..15)

    int i = beg;
    for (; i + 4 <= end; i += 4) {
        // issue all loads for 4 edges before any compute
        int s0 = g_srcs[i],     s1 = g_srcs[i + 1];
        int s2 = g_srcs[i + 2], s3 = g_srcs[i + 3];
        float2 se0 = seL[i],     se1 = seL[i + 1];
        float2 se2 = seL[i + 2], se3 = seL[i + 3];
        float2 sj0 = g_sj[s0], sj1 = g_sj[s1], sj2 = g_sj[s2], sj3 = g_sj[s3];
        uint2 r0 = ((const uint2*)(g_xph + (size_t)s0 * D))[lane];
        uint2 r1 = ((const uint2*)(g_xph + (size_t)s1 * D))[lane];
        uint2 r2 = ((const uint2*)(g_xph + (size_t)s2 * D))[lane];
        uint2 r3 = ((const uint2*)(g_xph + (size_t)s3 * D))[lane];

        float w0 = 1.f / (1.f + __expf(-sgn * (lrelu(si.x + sj0.x + se0.x) - lrelu(si.y + sj0.y + se0.y))));
        float w1 = 1.f / (1.f + __expf(-sgn * (lrelu(si.x + sj1.x + se1.x) - lrelu(si.y + sj1.y + se1.y))));
        float w2 = 1.f / (1.f + __expf(-sgn * (lrelu(si.x + sj2.x + se2.x) - lrelu(si.y + sj2.y + se2.y))));
        float w3 = 1.f / (1.f + __expf(-sgn * (lrelu(si.x + sj3.x + se3.x) - lrelu(si.y + sj3.y + se3.y))));

        float2 f0, f1;
        f0 = __half22float2(*reinterpret_cast<__half2*>(&r0.x));
        f1 = __half22float2(*reinterpret_cast<__half2*>(&r0.y));
        acc.x += w0 * f0.x; acc.y += w0 * f0.y; acc.z += w0 * f1.x; acc.w += w0 * f1.y;
        f0 = __half22float2(*reinterpret_cast<__half2*>(&r1.x));
        f1 = __half22float2(*reinterpret_cast<__half2*>(&r1.y));
        acc.x += w1 * f0.x; acc.y += w1 * f0.y; acc.z += w1 * f1.x; acc.w += w1 * f1.y;
        f0 = __half22float2(*reinterpret_cast<__half2*>(&r2.x));
        f1 = __half22float2(*reinterpret_cast<__half2*>(&r2.y));
        acc.x += w2 * f0.x; acc.y += w2 * f0.y; acc.z += w2 * f1.x; acc.w += w2 * f1.y;
        f0 = __half22float2(*reinterpret_cast<__half2*>(&r3.x));
        f1 = __half22float2(*reinterpret_cast<__half2*>(&r3.y));
        acc.x += w3 * f0.x; acc.y += w3 * f0.y; acc.z += w3 * f1.x; acc.w += w3 * f1.y;
    }
    for (; i < end; i++) {
        int s0 = g_srcs[i];
        float2 se0 = seL[i];
        float2 sj0 = g_sj[s0];
        uint2 r0 = ((const uint2*)(g_xph + (size_t)s0 * D))[lane];
        float w0 = 1.f / (1.f + __expf(-sgn * (lrelu(si.x + sj0.x + se0.x) - lrelu(si.y + sj0.y + se0.y))));
        float2 f0 = __half22float2(*reinterpret_cast<__half2*>(&r0.x));
        float2 f1 = __half22float2(*reinterpret_cast<__half2*>(&r0.y));
        acc.x += w0 * f0.x; acc.y += w0 * f0.y; acc.z += w0 * f1.x; acc.w += w0 * f1.y;
    }
    float4 bv = ((const float4*)b)[lane];
    acc.x = fmaxf(acc.x + bv.x, 0.f);
    acc.y = fmaxf(acc.y + bv.y, 0.f);
    acc.z = fmaxf(acc.z + bv.z, 0.f);
    acc.w = fmaxf(acc.w + bv.w, 0.f);
    ((float4*)(g_h + (size_t)node * D))[lane] = acc;
}

// ------------- mean pool: batch is sorted, run-length local accum --------
__global__ void pool_kernel(const void* __restrict__ batch) {
    const int NPB = 128;
    int t  = threadIdx.x;
    int n0 = blockIdx.x * NPB;
    int is64 = g_flags[1];
    float acc = 0.f; int cur = -1; int run = 0;
    for (int k = 0; k < NPB; k++) {
        int n = n0 + k;
        if (n >= N_NODES) break;
        int g = is64 ? (int)((const long long*)batch)[n] : ((const int*)batch)[n];
        if (g != cur) {
            if (cur >= 0) {
                atomicAdd(&g_pool[cur * D + t], acc);
                if (t == 0) atomicAdd(&g_cnt[cur], (float)run);
            }
            acc = 0.f; run = 0; cur = g;
        }
        acc += g_h[n * D + t]; run++;
    }
    if (cur >= 0) {
        atomicAdd(&g_pool[cur * D + t], acc);
        if (t == 0) atomicAdd(&g_cnt[cur], (float)run);
    }
}

// --------- final: warp per graph — mean, linear(128->2), log_softmax -----
__global__ void final_kernel(const float* __restrict__ wout,
                             const float* __restrict__ bout,
                             float* __restrict__ out) {
    int g    = (blockIdx.x * blockDim.x + threadIdx.x) >> 5;
    int lane = threadIdx.x & 31;
    if (g >= N_GRAPHS) return;
    float inv = 1.f / fmaxf(g_cnt[g], 1.f);
    float z0 = 0.f, z1 = 0.f;
    #pragma unroll
    for (int k = 0; k < 4; k++) {
        int c = lane + k * 32;
        float p = g_pool[g * D + c] * inv;
        z0 += p * wout[c * 2];
        z1 += p * wout[c * 2 + 1];
    }
    #pragma unroll
    for (int o = 16; o; o >>= 1) {
        z0 += __shfl_down_sync(0xffffffffu, z0, o);
        z1 += __shfl_down_sync(0xffffffffu, z1, o);
    }
    if (lane == 0) {
        z0 += bout[0]; z1 += bout[1];
        float m = fmaxf(z0, z1);
        float l = m + logf(expf(z0 - m) + expf(z1 - m));
        out[g * 2]     = z0 - l;
        out[g * 2 + 1] = z1 - l;
    }
}

// ------------------------------ launch -----------------------------------
extern "C" void kernel_launch(void* const* d_in, const int* in_sizes, int n_in,
                              void* d_out, int out_size) {
    const float* x     = (const float*)d_in[0];
    const void*  ei    = d_in[1];
    const float* ea    = (const float*)d_in[2];
    const void*  batch = d_in[3];
    const float* wl[3]  = { (const float*)d_in[4],  (const float*)d_in[8],  (const float*)d_in[12] };
    const float* we[3]  = { (const float*)d_in[5],  (const float*)d_in[9],  (const float*)d_in[13] };
    const float* att[3] = { (const float*)d_in[6],  (const float*)d_in[10], (const float*)d_in[14] };
    const float* bb[3]  = { (const float*)d_in[7],  (const float*)d_in[11], (const float*)d_in[15] };
    const float* wout = (const float*)d_in[16];
    const float* bout = (const float*)d_in[17];

    void *p_h = nullptr, *p_pool = nullptr, *p_cnt = nullptr, *p_deg = nullptr;
    cudaGetSymbolAddress(&p_h,    g_h);
    cudaGetSymbolAddress(&p_pool, g_pool);
    cudaGetSymbolAddress(&p_cnt,  g_cnt);
    cudaGetSymbolAddress(&p_deg,  g_deg);

    const int EB = (N_EDGES + 255) / 256;
    const int ND = N_NODES * D;

    init_kernel<<<1, 64>>>((const int*)ei, (const int*)batch,
                           we[0], att[0], we[1], att[1], we[2], att[2]);

    // CSR build + sorted se (once per call)
    cudaMemsetAsync(p_deg, 0, (size_t)N_NODES * sizeof(int));
    deg_kernel<<<EB, 256>>>(ei);
    scan1_kernel<<<SCAN_B, 256>>>();
    scan2_kernel<<<1, 256>>>();
    scan3_kernel<<<SCAN_B, 256>>>();
    scatter_kernel<<<EB, 256>>>(ei, ea);

    for (int l = 0; l < 3; l++) {
        if (l == 0) {
            lin0_kernel<<<(ND + 255) / 256, 256>>>(x, wl[0]);
            s_kernel<<<(N_NODES * 32 + 255) / 256, 256>>>(att[0]);
        } else {
            lin128_kernel<<<(N_NODES + 63) / 64, 256>>>((const float*)p_h, wl[l], att[l]);
        }
        agg_kernel<<<(N_NODES * 32 + 255) / 256, 256>>>(bb[l], l);
    }

    cudaMemsetAsync(p_pool, 0, (size_t)N_GRAPHS * D * sizeof(float));
    cudaMemsetAsync(p_cnt,  0, (size_t)N_GRAPHS * sizeof(float));
    pool_kernel<<<(N_NODES + 127) / 128, 128>>>(batch);
    final_kernel<<<2, 1024>>>(wout, bout, (float*)d_out);
}

// round 8
// speedup vs baseline: 1.2212x; 1.2212x over previous
#include <cuda_runtime.h>
#include <cuda_fp16.h>
#include <mma.h>
#include <math.h>

using namespace nvcuda;

#define N_NODES 50000
#define N_EDGES 640000
#define N_GRAPHS 64
#define D 128
#define SCAN_B ((N_NODES + 255) / 256)   // 196

// ---------------- device scratch (no allocation allowed) ----------------
__device__ __half  g_xph[N_NODES * D];   // xp in fp16 (gather operand)
__device__ float   g_h [N_NODES * D];    // layer output fp32 (for pool)
__device__ __half  g_hh[N_NODES * D];    // layer output fp16 (GEMM A operand)
__device__ float2  g_si[N_NODES];        // per-node dst-attention dots (2 heads)
__device__ float2  g_sj[N_NODES];        // per-node src-attention dots
__device__ float   g_ae[36];             // 3 layers x 6 feats x 2 heads
__device__ float2  g_seS[3 * N_EDGES];   // per-edge edge-att scores, dst-sorted, per layer
__device__ int     g_srcs[N_EDGES];      // src ids sorted by dst
__device__ int     g_deg[N_NODES];
__device__ int     g_off[N_NODES + 1];
__device__ int     g_cur[N_NODES];
__device__ int     g_bsum[SCAN_B];
__device__ float   g_pool[N_GRAPHS * D];
__device__ float   g_cnt[N_GRAPHS];
__device__ int     g_flags[2];           // [0]: edge_index is int64, [1]: batch is int64

// -------- init: dtype detection + per-layer edge-att projection ----------
__global__ void init_kernel(const int* __restrict__ ei32, const int* __restrict__ b32,
                            const float* __restrict__ we0, const float* __restrict__ at0,
                            const float* __restrict__ we1, const float* __restrict__ at1,
                            const float* __restrict__ we2, const float* __restrict__ at2) {
    __shared__ int s_e, s_b;
    int t = threadIdx.x;
    if (t == 0) { s_e = 0; s_b = 0; }
    __syncthreads();
    int ei_idx = 2 * (t * 257) + 1;
    if (ei32[ei_idx] != 0) atomicAdd(&s_e, 1);
    int b_idx = (N_NODES - 1) - 2 * t;     // batch sorted: sample near tail
    if (b32[b_idx] != 0) atomicAdd(&s_b, 1);
    __syncthreads();
    if (t == 0) { g_flags[0] = (s_e == 0); g_flags[1] = (s_b == 0); }
    if (t < 36) {
        int l = t / 12, r = t % 12, f = r / 2, h = r % 2;
        const float* we = (l == 0) ? we0 : (l == 1) ? we1 : we2;
        const float* at = (l == 0) ? at0 : (l == 1) ? at1 : at2;
        float s = 0.f;
        #pragma unroll
        for (int c = 0; c < 64; c++)
            s += we[f * 128 + h * 64 + c] * at[h * 192 + 128 + c];
        g_ae[t] = s;
    }
}

__device__ __forceinline__ void load_edge(const void* ei, int e, int& src, int& dst) {
    if (g_flags[0]) {
        const long long* p = (const long long*)ei;
        src = (int)p[e]; dst = (int)p[N_EDGES + e];
    } else {
        const int* p = (const int*)ei;
        src = p[e]; dst = p[N_EDGES + e];
    }
}

// ---------------------------- CSR build ----------------------------------
__global__ void deg_kernel(const void* __restrict__ ei) {
    int e = blockIdx.x * blockDim.x + threadIdx.x;
    if (e >= N_EDGES) return;
    int src, dst; load_edge(ei, e, src, dst);
    atomicAdd(&g_deg[dst], 1);
}

__global__ void scan1_kernel() {              // SCAN_B blocks x 256
    __shared__ int sh[256];
    int t = threadIdx.x;
    int i = blockIdx.x * 256 + t;
    int v = (i < N_NODES) ? g_deg[i] : 0;
    sh[t] = v; __syncthreads();
    #pragma unroll
    for (int off = 1; off < 256; off <<= 1) {
        int u = (t >= off) ? sh[t - off] : 0;
        __syncthreads();
        sh[t] += u;
        __syncthreads();
    }
    if (i < N_NODES) g_off[i] = sh[t] - v;    // block-local exclusive
    if (t == 255) g_bsum[blockIdx.x] = sh[255];
}

__global__ void scan2_kernel() {              // 1 block x 256
    __shared__ int sh[256];
    int t = threadIdx.x;
    int v = (t < SCAN_B) ? g_bsum[t] : 0;
    sh[t] = v; __syncthreads();
    #pragma unroll
    for (int off = 1; off < 256; off <<= 1) {
        int u = (t >= off) ? sh[t - off] : 0;
        __syncthreads();
        sh[t] += u;
        __syncthreads();
    }
    if (t < SCAN_B) g_bsum[t] = sh[t] - v;    // exclusive block prefix
}

__global__ void scan3_kernel() {              // SCAN_B blocks x 256
    int i = blockIdx.x * 256 + threadIdx.x;
    if (i < N_NODES) {
        int o = g_off[i] + g_bsum[blockIdx.x];
        g_off[i] = o; g_cur[i] = o;
    }
    if (i == 0) g_off[N_NODES] = N_EDGES;
}

// scatter src + per-edge se (all 3 layers) into dst-sorted order
__global__ void scatter_kernel(const void* __restrict__ ei,
                               const float* __restrict__ ea) {
    int e = blockIdx.x * blockDim.x + threadIdx.x;
    if (e >= N_EDGES) return;
    int src, dst; load_edge(ei, e, src, dst);
    int pos = atomicAdd(&g_cur[dst], 1);
    g_srcs[pos] = src;
    float f[6];
    #pragma unroll
    for (int k = 0; k < 6; k++) f[k] = __ldg(ea + e * 6 + k);
    #pragma unroll
    for (int l = 0; l < 3; l++) {
        const float* ap = g_ae + l * 12;
        float s0 = 0.f, s1 = 0.f;
        #pragma unroll
        for (int k = 0; k < 6; k++) { s0 += f[k] * ap[k * 2]; s1 += f[k] * ap[k * 2 + 1]; }
        g_seS[l * N_EDGES + pos] = make_float2(s0, s1);
    }
}

// ---------------- layer-0 lin: x(N,7) @ w(7,128) -> g_xph ----------------
__global__ void lin0_kernel(const float* __restrict__ x, const float* __restrict__ w) {
    int idx = blockIdx.x * blockDim.x + threadIdx.x;
    if (idx >= N_NODES * D) return;
    int n = idx >> 7, c = idx & 127;
    const float* xr = x + n * 7;
    float s = 0.f;
    #pragma unroll
    for (int f = 0; f < 7; f++) s += xr[f] * w[f * 128 + c];
    g_xph[idx] = __float2half_rn(s);
}

// ------------- per-node attention dots for layer 0 (reads fp16 xp) -------
__global__ void s_kernel(const float* __restrict__ att) {
    int node = (blockIdx.x * blockDim.x + threadIdx.x) >> 5;
    int lane = threadIdx.x & 31;
    if (node >= N_NODES) return;
    uint2 raw = ((const uint2*)(g_xph + (size_t)node * D))[lane];
    __half2 p0 = *reinterpret_cast<__half2*>(&raw.x);
    __half2 p1 = *reinterpret_cast<__half2*>(&raw.y);
    float2 f0 = __half22float2(p0), f1 = __half22float2(p1);
    float v[4] = { f0.x, f0.y, f1.x, f1.y };
    float si_p = 0.f, sj_p = 0.f;
    int c0 = lane * 4;
    int h  = c0 >> 6;
    const float* ai = att + h * 192;
    const float* aj = att + h * 192 + 64;
    #pragma unroll
    for (int k = 0; k < 4; k++) {
        int cc = (c0 & 63) + k;
        si_p += v[k] * ai[cc];
        sj_p += v[k] * aj[cc];
    }
    #pragma unroll
    for (int o = 8; o; o >>= 1) {
        si_p += __shfl_down_sync(0xffffffffu, si_p, o, 16);
        sj_p += __shfl_down_sync(0xffffffffu, sj_p, o, 16);
    }
    float si1 = __shfl_sync(0xffffffffu, si_p, 16);
    float sj1 = __shfl_sync(0xffffffffu, sj_p, 16);
    if (lane == 0) {
        g_si[node] = make_float2(si_p, si1);
        g_sj[node] = make_float2(sj_p, sj1);
    }
}

// ---- lin (layers 1,2): hh(N,128)fp16 @ w(128,128) -> g_xph + s-dots -----
// WMMA 16x16x16, fp32 accumulate. Block = 64 rows, 8 warps.
// smem: A[64][136]h + B[64][136]h during K loop; C[64][132]f reuses same space.
__global__ void __launch_bounds__(256) lin128_wmma(const __half* __restrict__ hh,
                                                   const float* __restrict__ w,
                                                   const float* __restrict__ att) {
    __shared__ __align__(32) unsigned char smem_raw[34816];
    __half* As = (__half*)smem_raw;                 // [64][136]
    __half* Bs = (__half*)(smem_raw + 17408);       // [64][136] (one 64-K chunk)
    float*  Cs = (float*)smem_raw;                  // [64][132] after K loop

    int t = threadIdx.x;
    int wid = t >> 5, lane = t & 31;
    int row0 = blockIdx.x * 64;

    // load A: 64 rows x 128 cols fp16 (zero-pad OOB rows)
    for (int i = t; i < 64 * 32; i += 256) {
        int r = i >> 5, g = i & 31;
        int row = row0 + r;
        uint2 v = make_uint2(0u, 0u);
        if (row < N_NODES) v = *(const uint2*)(hh + (size_t)row * 128 + g * 4);
        *(uint2*)(As + r * 136 + g * 4) = v;
    }

    wmma::fragment<wmma::accumulator, 16, 16, 16, float> c[4];
    #pragma unroll
    for (int j = 0; j < 4; j++) wmma::fill_fragment(c[j], 0.f);

    int m_tile = wid & 3;        // 4 M-tiles of 16 rows
    int n_half = wid >> 2;       // 2 N-halves of 64 cols

    for (int kc = 0; kc < 2; kc++) {
        int k0 = kc * 64;
        // load B chunk: w[k0..k0+63][0..127] fp32 -> fp16
        for (int i = t; i < 64 * 32; i += 256) {
            int r = i >> 5, g = i & 31;
            float4 v = *(const float4*)(w + (size_t)(k0 + r) * 128 + g * 4);
            *(__half2*)(Bs + r * 136 + g * 4)     = __floats2half2_rn(v.x, v.y);
            *(__half2*)(Bs + r * 136 + g * 4 + 2) = __floats2half2_rn(v.z, v.w);
        }
        __syncthreads();
        #pragma unroll
        for (int kk = 0; kk < 4; kk++) {
            int k = k0 + kk * 16;
            wmma::fragment<wmma::matrix_a, 16, 16, 16, __half, wmma::row_major> a;
            wmma::load_matrix_sync(a, As + m_tile * 16 * 136 + k, 136);
            #pragma unroll
            for (int j = 0; j < 4; j++) {
                wmma::fragment<wmma::matrix_b, 16, 16, 16, __half, wmma::row_major> b;
                wmma::load_matrix_sync(b, Bs + (kk * 16) * 136 + n_half * 64 + j * 16, 136);
                wmma::mma_sync(c[j], a, b, c[j]);
            }
        }
        __syncthreads();
    }

    // stage C into shared (overwrites As/Bs; all mma reads done)
    #pragma unroll
    for (int j = 0; j < 4; j++)
        wmma::store_matrix_sync(Cs + m_tile * 16 * 132 + n_half * 64 + j * 16,
                                c[j], 132, wmma::mem_row_major);
    __syncthreads();

    // epilogue: warp handles rows wid*8..wid*8+7 — fp16 xp store + s-dots
    for (int r8 = 0; r8 < 8; r8++) {
        int r = wid * 8 + r8;
        int row = row0 + r;
        if (row >= N_NODES) break;
        const float* cr = Cs + r * 132;
        float v0 = cr[lane * 4], v1 = cr[lane * 4 + 1];
        float v2 = cr[lane * 4 + 2], v3 = cr[lane * 4 + 3];
        ((__half2*)(g_xph + (size_t)row * 128))[lane * 2]     = __floats2half2_rn(v0, v1);
        ((__half2*)(g_xph + (size_t)row * 128))[lane * 2 + 1] = __floats2half2_rn(v2, v3);
        int c0 = lane * 4;
        int h  = c0 >> 6;
        const float* ai = att + h * 192;
        const float* aj = att + h * 192 + 64;
        int cc = c0 & 63;
        float si_p = v0 * ai[cc] + v1 * ai[cc + 1] + v2 * ai[cc + 2] + v3 * ai[cc + 3];
        float sj_p = v0 * aj[cc] + v1 * aj[cc + 1] + v2 * aj[cc + 2] + v3 * aj[cc + 3];
        #pragma unroll
        for (int o = 8; o; o >>= 1) {
            si_p += __shfl_down_sync(0xffffffffu, si_p, o, 16);
            sj_p += __shfl_down_sync(0xffffffffu, sj_p, o, 16);
        }
        float si1 = __shfl_sync(0xffffffffu, si_p, 16);
        float sj1 = __shfl_sync(0xffffffffu, sj_p, 16);
        if (lane == 0) {
            g_si[row] = make_float2(si_p, si1);
            g_sj[row] = make_float2(sj_p, sj1);
        }
    }
}

// ------- aggregate: warp/dst, 2-edge unrolled (R6-verified), sigmoid -----
__device__ __forceinline__ float lrelu(float v) { return v > 0.f ? v : 0.2f * v; }

__global__ void __launch_bounds__(256) agg_kernel(const float* __restrict__ b, int layer) {
    int node = (blockIdx.x * blockDim.x + threadIdx.x) >> 5;
    int lane = threadIdx.x & 31;
    if (node >= N_NODES) return;
    int beg = g_off[node], end = g_off[node + 1];
    float2 si = g_si[node];
    const float2* seL = g_seS + (size_t)layer * N_EDGES;
    float4 acc = make_float4(0.f, 0.f, 0.f, 0.f);
    float sgn = (lane < 16) ? 1.f : -1.f;     // head0 = cols 0..63 (lanes 0..15)

    int i = beg;
    for (; i + 2 <= end; i += 2) {
        int s0 = g_srcs[i], s1 = g_srcs[i + 1];
        float2 se0 = seL[i], se1 = seL[i + 1];
        float2 sj0 = g_sj[s0], sj1 = g_sj[s1];
        uint2 r0 = ((const uint2*)(g_xph + (size_t)s0 * D))[lane];
        uint2 r1 = ((const uint2*)(g_xph + (size_t)s1 * D))[lane];

        float d0 = lrelu(si.x + sj0.x + se0.x) - lrelu(si.y + sj0.y + se0.y);
        float w0 = 1.f / (1.f + __expf(-sgn * d0));
        float2 f0 = __half22float2(*reinterpret_cast<__half2*>(&r0.x));
        float2 f1 = __half22float2(*reinterpret_cast<__half2*>(&r0.y));
        acc.x += w0 * f0.x; acc.y += w0 * f0.y;
        acc.z += w0 * f1.x; acc.w += w0 * f1.y;

        float d1 = lrelu(si.x + sj1.x + se1.x) - lrelu(si.y + sj1.y + se1.y);
        float w1 = 1.f / (1.f + __expf(-sgn * d1));
        float2 g0 = __half22float2(*reinterpret_cast<__half2*>(&r1.x));
        float2 g1 = __half22float2(*reinterpret_cast<__half2*>(&r1.y));
        acc.x += w1 * g0.x; acc.y += w1 * g0.y;
        acc.z += w1 * g1.x; acc.w += w1 * g1.y;
    }
    if (i < end) {
        int s0 = g_srcs[i];
        float2 se0 = seL[i];
        float2 sj0 = g_sj[s0];
        uint2 r0 = ((const uint2*)(g_xph + (size_t)s0 * D))[lane];
        float d0 = lrelu(si.x + sj0.x + se0.x) - lrelu(si.y + sj0.y + se0.y);
        float w0 = 1.f / (1.f + __expf(-sgn * d0));
        float2 f0 = __half22float2(*reinterpret_cast<__half2*>(&r0.x));
        float2 f1 = __half22float2(*reinterpret_cast<__half2*>(&r0.y));
        acc.x += w0 * f0.x; acc.y += w0 * f0.y;
        acc.z += w0 * f1.x; acc.w += w0 * f1.y;
    }
    float4 bv = ((const float4*)b)[lane];
    acc.x = fmaxf(acc.x + bv.x, 0.f);
    acc.y = fmaxf(acc.y + bv.y, 0.f);
    acc.z = fmaxf(acc.z + bv.z, 0.f);
    acc.w = fmaxf(acc.w + bv.w, 0.f);
    ((float4*)(g_h + (size_t)node * D))[lane] = acc;
    // fp16 copy for the tensor-core GEMM A-operand
    ((__half2*)(g_hh + (size_t)node * D))[lane * 2]     = __floats2half2_rn(acc.x, acc.y);
    ((__half2*)(g_hh + (size_t)node * D))[lane * 2 + 1] = __floats2half2_rn(acc.z, acc.w);
}

// ------------- mean pool: batch is sorted, run-length local accum --------
__global__ void pool_kernel(const void* __restrict__ batch) {
    const int NPB = 128;
    int t  = threadIdx.x;
    int n0 = blockIdx.x * NPB;
    int is64 = g_flags[1];
    float acc = 0.f; int cur = -1; int run = 0;
    for (int k = 0; k < NPB; k++) {
        int n = n0 + k;
        if (n >= N_NODES) break;
        int g = is64 ? (int)((const long long*)batch)[n] : ((const int*)batch)[n];
        if (g != cur) {
            if (cur >= 0) {
                atomicAdd(&g_pool[cur * D + t], acc);
                if (t == 0) atomicAdd(&g_cnt[cur], (float)run);
            }
            acc = 0.f; run = 0; cur = g;
        }
        acc += g_h[n * D + t]; run++;
    }
    if (cur >= 0) {
        atomicAdd(&g_pool[cur * D + t], acc);
        if (t == 0) atomicAdd(&g_cnt[cur], (float)run);
    }
}

// --------- final: warp per graph — mean, linear(128->2), log_softmax -----
__global__ void final_kernel(const float* __restrict__ wout,
                             const float* __restrict__ bout,
                             float* __restrict__ out) {
    int g    = (blockIdx.x * blockDim.x + threadIdx.x) >> 5;
    int lane = threadIdx.x & 31;
    if (g >= N_GRAPHS) return;
    float inv = 1.f / fmaxf(g_cnt[g], 1.f);
    float z0 = 0.f, z1 = 0.f;
    #pragma unroll
    for (int k = 0; k < 4; k++) {
        int c = lane + k * 32;
        float p = g_pool[g * D + c] * inv;
        z0 += p * wout[c * 2];
        z1 += p * wout[c * 2 + 1];
    }
    #pragma unroll
    for (int o = 16; o; o >>= 1) {
        z0 += __shfl_down_sync(0xffffffffu, z0, o);
        z1 += __shfl_down_sync(0xffffffffu, z1, o);
    }
    if (lane == 0) {
        z0 += bout[0]; z1 += bout[1];
        float m = fmaxf(z0, z1);
        float l = m + logf(expf(z0 - m) + expf(z1 - m));
        out[g * 2]     = z0 - l;
        out[g * 2 + 1] = z1 - l;
    }
}

// ------------------------------ launch -----------------------------------
extern "C" void kernel_launch(void* const* d_in, const int* in_sizes, int n_in,
                              void* d_out, int out_size) {
    const float* x     = (const float*)d_in[0];
    const void*  ei    = d_in[1];
    const float* ea    = (const float*)d_in[2];
    const void*  batch = d_in[3];
    const float* wl[3]  = { (const float*)d_in[4],  (const float*)d_in[8],  (const float*)d_in[12] };
    const float* we[3]  = { (const float*)d_in[5],  (const float*)d_in[9],  (const float*)d_in[13] };
    const float* att[3] = { (const float*)d_in[6],  (const float*)d_in[10], (const float*)d_in[14] };
    const float* bb[3]  = { (const float*)d_in[7],  (const float*)d_in[11], (const float*)d_in[15] };
    const float* wout = (const float*)d_in[16];
    const float* bout = (const float*)d_in[17];

    void *p_hh = nullptr, *p_pool = nullptr, *p_cnt = nullptr, *p_deg = nullptr;
    cudaGetSymbolAddress(&p_hh,   g_hh);
    cudaGetSymbolAddress(&p_pool, g_pool);
    cudaGetSymbolAddress(&p_cnt,  g_cnt);
    cudaGetSymbolAddress(&p_deg,  g_deg);

    const int EB = (N_EDGES + 255) / 256;
    const int ND = N_NODES * D;

    init_kernel<<<1, 64>>>((const int*)ei, (const int*)batch,
                           we[0], att[0], we[1], att[1], we[2], att[2]);

    // CSR build + sorted se (once per call)
    cudaMemsetAsync(p_deg, 0, (size_t)N_NODES * sizeof(int));
    deg_kernel<<<EB, 256>>>(ei);
    scan1_kernel<<<SCAN_B, 256>>>();
    scan2_kernel<<<1, 256>>>();
    scan3_kernel<<<SCAN_B, 256>>>();
    scatter_kernel<<<EB, 256>>>(ei, ea);

    for (int l = 0; l < 3; l++) {
        if (l == 0) {
            lin0_kernel<<<(ND + 255) / 256, 256>>>(x, wl[0]);
            s_kernel<<<(N_NODES * 32 + 255) / 256, 256>>>(att[0]);
        } else {
            lin128_wmma<<<(N_NODES + 63) / 64, 256>>>((const __half*)p_hh, wl[l], att[l]);
        }
        agg_kernel<<<(N_NODES * 32 + 255) / 256, 256>>>(bb[l], l);
    }

    cudaMemsetAsync(p_pool, 0, (size_t)N_GRAPHS * D * sizeof(float));
    cudaMemsetAsync(p_cnt,  0, (size_t)N_GRAPHS * sizeof(float));
    pool_kernel<<<(N_NODES + 127) / 128, 128>>>(batch);
    final_kernel<<<2, 1024>>>(wout, bout, (float*)d_out);
}